// round 13
// baseline (speedup 1.0000x reference)
#include <cuda_runtime.h>
#include <cuda_bf16.h>
#include <math.h>
#include <stdint.h>

#define DIM    1024
#define HD     128
#define FF     4096
#define VOC    2048
#define NLM    15
#define NLAYER 5
#define EPSF   1e-6f
#define NBLK   148
#define CTHR   512
#define NTHR   544
#define NWARP  16

#define NBUF         12
#define STAGE_BYTES  16384
#define STAGE_FLOATS 4096
#define MBF_OFF  0
#define MBE_OFF  96
#define SC_OFF   192        // up to 8 floats (2 stages x {e0,e1,inv})
#define XS_OFF   256        // 4KB: float2[32] for phases, float[1024] for LM
#define SBUF_OFF 4352
#define TAB_OFF  4480       // 240 ptrs
#define ST_OFF   8192
#define SM_TOTAL (ST_OFF + NBUF * STAGE_BYTES)   // 204800

#define N_STICKY_MATS 6

// phase stage counts (per layer; LM once)
#define S_QKV 768
#define S_WO  256
#define S_GU  2048
#define S_DN  1024
#define S_LM  7680

__device__ float g_h[2 * DIM];
__device__ float g_qkv[6 * DIM];
__device__ float g_gu[4 * FF];
__device__ unsigned g_bar[32];
__device__ unsigned g_fin;

__device__ __forceinline__ uint32_t s2u(const void* p) {
    uint32_t a;
    asm("{ .reg .u64 t; cvta.to.shared.u64 t, %1; cvt.u32.u64 %0, t; }"
        : "=r"(a) : "l"(p));
    return a;
}
#define MB_INIT(mbar, cnt) \
    asm volatile("mbarrier.init.shared.b64 [%0], %1;" :: "r"(mbar), "r"(cnt) : "memory")
#define MB_EXPECT(mbar, bytes) \
    asm volatile("mbarrier.arrive.expect_tx.shared.b64 _, [%0], %1;" :: "r"(mbar), "r"(bytes) : "memory")
#define MB_ARRIVE(mbar) \
    asm volatile("mbarrier.arrive.shared.b64 _, [%0];" :: "r"(mbar) : "memory")
#define MB_WAIT(mbar, ph) do {                                                   \
    asm volatile("{\n\t.reg .pred P1;\n\t"                                       \
        "W_%=:\n\t"                                                              \
        "mbarrier.try_wait.parity.acquire.cta.shared::cta.b64 P1, [%0], %1, 0x989680;\n\t" \
        "@P1 bra.uni D_%=;\n\t"                                                  \
        "bra.uni W_%=;\n\t"                                                      \
        "D_%=:\n\t}"                                                             \
        :: "r"(mbar), "r"(ph) : "memory");                                       \
} while (0)
#define CBAR() asm volatile("bar.sync 1, %0;" :: "n"(CTHR) : "memory")
__device__ __forceinline__ void bulk_g2s_h(uint32_t dst, const void* src,
                                           uint32_t bytes, uint32_t mbar,
                                           uint64_t pol) {
    asm volatile(
        "cp.async.bulk.shared::cluster.global.mbarrier::complete_tx::bytes"
        ".L2::cache_hint [%0], [%1], %2, [%3], %4;"
        :: "r"(dst), "l"(src), "r"(bytes), "r"(mbar), "l"(pol) : "memory");
}
__device__ __forceinline__ void red2(float* p, float a, float b) {
    asm volatile("red.global.add.v2.f32 [%0], {%1, %2};"
                 :: "l"(p), "f"(a), "f"(b) : "memory");
}
__device__ __forceinline__ void red4(float* p, float4 v) {
    asm volatile("red.global.add.v4.f32 [%0], {%1, %2, %3, %4};"
                 :: "l"(p), "f"(v.x), "f"(v.y), "f"(v.z), "f"(v.w) : "memory");
}
__device__ __forceinline__ float ldcg(const float* p) {
    float v;
    asm volatile("ld.global.cg.f32 %0, [%1];" : "=f"(v) : "l"(p));
    return v;
}
__device__ __forceinline__ float4 ldcg4(const float* p) {
    float4 v;
    asm volatile("ld.global.cg.v4.f32 {%0,%1,%2,%3}, [%4];"
                 : "=f"(v.x), "=f"(v.y), "=f"(v.z), "=f"(v.w) : "l"(p));
    return v;
}

__device__ __forceinline__ float wred(float v) {
#pragma unroll
    for (int o = 16; o > 0; o >>= 1) v += __shfl_xor_sync(0xffffffffu, v, o);
    return v;
}
__device__ __forceinline__ float bred512(float v, float* sbuf) {
    int tid = threadIdx.x;
#pragma unroll
    for (int o = 16; o > 0; o >>= 1) v += __shfl_down_sync(0xffffffffu, v, o);
    if ((tid & 31) == 0) sbuf[tid >> 5] = v;
    CBAR();
    if (tid < 32) {
        float r = (tid < 16) ? sbuf[tid] : 0.f;
#pragma unroll
        for (int o = 8; o > 0; o >>= 1) r += __shfl_down_sync(0xffffffffu, r, o);
        if (tid == 0) sbuf[0] = r;
    }
    CBAR();
    float r = sbuf[0];
    CBAR();
    return r;
}

__device__ __forceinline__ void gbar(int idx) {
    __threadfence();
    CBAR();
    if (threadIdx.x == 0) {
        atomicAdd(&g_bar[idx], 1u);
        unsigned v;
        while (true) {
            asm volatile("ld.acquire.gpu.global.u32 %0, [%1];"
                         : "=r"(v) : "l"(&g_bar[idx]) : "memory");
            if (v >= (unsigned)NBLK) break;
            __nanosleep(64);
        }
    }
    CBAR();
}

#define STAGE_WAIT()                                                           \
    int _slot = consumed % NBUF, _par = (consumed / NBUF) & 1;                 \
    MB_WAIT(mbf + 8u * _slot, _par);                                           \
    const float* buf = (const float*)(sm + ST_OFF + _slot * STAGE_BYTES);
#define STAGE_DONE()                                                           \
    __syncwarp();                                                              \
    if ((tid & 31) == 0) MB_ARRIVE(mbe + 8u * _slot);                          \
    consumed++;

__device__ __forceinline__ void srange(int b, int S, int& s0, int& s1) {
    s0 = (b * S) / NBLK;
    s1 = ((b + 1) * S) / NBLK;
}

// ---------------- mega kernel ----------------
__global__ void __launch_bounds__(NTHR) k_mega(
    const float* __restrict__ past, const float* __restrict__ emb,
    const int* __restrict__ tok,
    const float* __restrict__ Wq, const float* __restrict__ Wk,
    const float* __restrict__ Wv, const float* __restrict__ Wo,
    const float* __restrict__ qn, const float* __restrict__ kn,
    const float* __restrict__ ln1, const float* __restrict__ ln2,
    const float* __restrict__ Wg, const float* __restrict__ Wu,
    const float* __restrict__ Wd, const float* __restrict__ fn,
    const float* __restrict__ lm,
    float* __restrict__ logits, float* __restrict__ kvc) {
    extern __shared__ char sm[];
    const int b = blockIdx.x;
    const int tid = threadIdx.x;
    const uint32_t mbf = s2u(sm) + MBF_OFF;
    const uint32_t mbe = s2u(sm) + MBE_OFF;
    float* sbuf = (float*)(sm + SBUF_OFF);
    float2* xs2 = (float2*)(sm + XS_OFF);
    float* xsf = (float*)(sm + XS_OFF);
    float* sc = (float*)(sm + SC_OFF);
    int s0, s1;

    if (tid == CTHR) {
#pragma unroll
        for (int s = 0; s < NBUF; s++) {
            MB_INIT(mbf + 8u * s, 1);
            MB_INIT(mbe + 8u * s, NWARP);
        }
    }
    __syncthreads();

    // ================= producer warp =================
    if (tid >= CTHR) {
        if (tid == CTHR) {
            uint64_t pol_keep, pol_stream;
            asm volatile("createpolicy.fractional.L2::evict_last.b64 %0, 1.0;"
                         : "=l"(pol_keep));
            asm volatile("createpolicy.fractional.L2::evict_first.b64 %0, 1.0;"
                         : "=l"(pol_stream));
            uintptr_t* tab = (uintptr_t*)(sm + TAB_OFF);
            int n = 0;
            for (int l = 0; l < NLAYER; l++) {
                srange(b, S_QKV, s0, s1);
                for (int s = s0; s < s1; s++) {
                    int mat = s >> 8;
                    const float* W = mat == 0 ? Wq : (mat == 1 ? Wk : Wv);
                    tab[n++] = (uintptr_t)(W + (size_t)l * DIM * DIM +
                                           (size_t)(s & 255) * 4 * DIM);
                }
                srange(b, S_WO, s0, s1);
                for (int s = s0; s < s1; s++)
                    tab[n++] = (uintptr_t)(Wo + (size_t)l * DIM * DIM +
                                           (size_t)s * 4 * DIM);
                srange(b, S_GU, s0, s1);
                for (int s = s0; s < s1; s++) {
                    const float* W = (s >> 10) ? Wu : Wg;
                    tab[n++] = (uintptr_t)(W + (size_t)l * DIM * FF +
                                           (size_t)(s & 1023) * FF);
                }
                srange(b, S_DN, s0, s1);
                for (int s = s0; s < s1; s++)
                    tab[n++] = (uintptr_t)(Wd + (size_t)l * FF * DIM +
                                           (size_t)s * 4 * DIM);
            }
            srange(b, S_LM, s0, s1);
            for (int s = s0; s < s1; s++) {
                int mat = s / 512;
                uintptr_t flag = (mat < N_STICKY_MATS) ? 1u : 0u;
                tab[n++] = ((uintptr_t)(lm + (size_t)mat * DIM * VOC +
                                        (size_t)(s % 512) * 2 * VOC)) | flag;
            }
            for (int i = 0; i < n; i++) {
                int slot = i % NBUF;
                if (i >= NBUF) {
                    int par = ((i / NBUF) - 1) & 1;
                    MB_WAIT(mbe + 8u * slot, par);
                }
                uintptr_t e = tab[i];
                uint64_t pol = (e & 1u) ? pol_keep : pol_stream;
                const void* src = (const void*)(e & ~(uintptr_t)1u);
                MB_EXPECT(mbf + 8u * slot, STAGE_BYTES);
                bulk_g2s_h(s2u(sm) + ST_OFF + slot * STAGE_BYTES, src,
                           STAGE_BYTES, mbf + 8u * slot, pol);
            }
        }
        return;
    }

    // ================= compute threads (512) =================
    int consumed = 0;

    {   // init
        int gi = b * CTHR + tid;
        if (gi < NLM * VOC) logits[gi] = 0.f;
        else if (gi < NLM * VOC + 6 * DIM) g_qkv[gi - NLM * VOC] = 0.f;
        else if (gi < NLM * VOC + 6 * DIM + DIM) {
            int i = gi - (NLM * VOC + 6 * DIM);
            g_h[i] = past[i];
        } else if (gi < NLM * VOC + 6 * DIM + 2 * DIM) {
            int i = gi - (NLM * VOC + 7 * DIM);
            g_h[DIM + i] = emb[(size_t)tok[0] * DIM + i];
        }
    }
    gbar(0);

    for (int l = 0; l < NLAYER; l++) {
        // ===== QKV: all blocks, 5-6 stages of 4 rows =====
        {
            srange(b, S_QKV, s0, s1);
            int nst = s1 - s0;
            float q0 = 0.f, q1 = 0.f;
#pragma unroll
            for (int i = 0; i < 2; i++) {
                int idx = tid + i * CTHR;
                float a = ldcg(&g_h[idx]), c = ldcg(&g_h[DIM + idx]);
                q0 += a * a; q1 += c * c;
            }
            q0 = bred512(q0, sbuf);
            q1 = bred512(q1, sbuf);
            float r0 = rsqrtf(q0 * (1.f / DIM) + EPSF);
            float r1 = rsqrtf(q1 * (1.f / DIM) + EPSF);
            if (b < 32) g_gu[b * CTHR + tid] = 0.f;   // zero this layer's g_gu
            if (tid < 4 * nst) {
                int s = s0 + (tid >> 2);
                int row = (s & 255) * 4 + (tid & 3);
                float wl = ln1[l * DIM + row];
                xs2[tid] = make_float2(ldcg(&g_h[row]) * r0 * wl,
                                       ldcg(&g_h[DIM + row]) * r1 * wl);
            }
            CBAR();
            float a00 = 0.f, a01 = 0.f, a10 = 0.f, a11 = 0.f;
            int curmat = -1;
            for (int si = 0; si < nst; si++) {
                int s = s0 + si;
                int mat = s >> 8;
                if (mat != curmat) {
                    if (curmat >= 0) {
                        float* o = g_qkv + curmat * 2048;
                        red2(o + 2 * tid, a00, a01);
                        red2(o + DIM + 2 * tid, a10, a11);
                        a00 = a01 = a10 = a11 = 0.f;
                    }
                    curmat = mat;
                }
                STAGE_WAIT()
                const float2* bw = (const float2*)buf;
#pragma unroll
                for (int r = 0; r < 4; r++) {
                    float2 w = bw[r * CTHR + tid];
                    float2 x = xs2[si * 4 + r];
                    a00 = fmaf(w.x, x.x, a00); a01 = fmaf(w.y, x.x, a01);
                    a10 = fmaf(w.x, x.y, a10); a11 = fmaf(w.y, x.y, a11);
                }
                STAGE_DONE()
            }
            if (curmat >= 0) {
                float* o = g_qkv + curmat * 2048;
                red2(o + 2 * tid, a00, a01);
                red2(o + DIM + 2 * tid, a10, a11);
            }
        }
        gbar(1 + 4 * l);

        // ===== WO + attention: all blocks, 1-2 stages of 4 rows =====
        {
            srange(b, S_WO, s0, s1);
            int nst = s1 - s0;
            if (tid < 32) {
                int lane = tid;
                for (int si = 0; si < nst; si++) {
                    int s = s0 + si;
                    int hh = s >> 5;   // 32 stages per head
                    float4 q1v = ldcg4(g_qkv + DIM + hh * HD + 4 * lane);
                    float4 k0 = ldcg4(g_qkv + 2048 + hh * HD + 4 * lane);
                    float4 k1 = ldcg4(g_qkv + 2048 + DIM + hh * HD + 4 * lane);
                    float nq1 = wred(q1v.x * q1v.x + q1v.y * q1v.y +
                                     q1v.z * q1v.z + q1v.w * q1v.w);
                    float nk0 = wred(k0.x * k0.x + k0.y * k0.y + k0.z * k0.z + k0.w * k0.w);
                    float nk1 = wred(k1.x * k1.x + k1.y * k1.y + k1.z * k1.z + k1.w * k1.w);
                    float rq1 = rsqrtf(nq1 * (1.f / HD) + EPSF);
                    float rk0 = rsqrtf(nk0 * (1.f / HD) + EPSF);
                    float rk1 = rsqrtf(nk1 * (1.f / HD) + EPSF);
                    float4 qn4 = ((const float4*)(qn + l * HD))[lane];
                    float4 kn4 = ((const float4*)(kn + l * HD))[lane];
                    q1v.x *= rq1 * qn4.x; q1v.y *= rq1 * qn4.y;
                    q1v.z *= rq1 * qn4.z; q1v.w *= rq1 * qn4.w;
                    k0.x *= rk0 * kn4.x; k0.y *= rk0 * kn4.y;
                    k0.z *= rk0 * kn4.z; k0.w *= rk0 * kn4.w;
                    k1.x *= rk1 * kn4.x; k1.y *= rk1 * kn4.y;
                    k1.z *= rk1 * kn4.z; k1.w *= rk1 * kn4.w;
                    int jb = 4 * (lane & 15);
                    const float C = 9.210340371976184f / 64.f;
                    float an0 = expf(-(float)(jb + 0) * C);
                    float an1 = expf(-(float)(jb + 1) * C);
                    float an2 = expf(-(float)(jb + 2) * C);
                    float an3 = expf(-(float)(jb + 3) * C);
                    float csx = cosf(an0), snx = sinf(an0);
                    float csy = cosf(an1), sny = sinf(an1);
                    float csz = cosf(an2), snz = sinf(an2);
                    float csw = cosf(an3), snw = sinf(an3);
                    float sgn = (lane < 16) ? -1.f : 1.f;
                    float4 pq, pk;
                    pq.x = __shfl_xor_sync(0xffffffffu, q1v.x, 16);
                    pq.y = __shfl_xor_sync(0xffffffffu, q1v.y, 16);
                    pq.z = __shfl_xor_sync(0xffffffffu, q1v.z, 16);
                    pq.w = __shfl_xor_sync(0xffffffffu, q1v.w, 16);
                    pk.x = __shfl_xor_sync(0xffffffffu, k1.x, 16);
                    pk.y = __shfl_xor_sync(0xffffffffu, k1.y, 16);
                    pk.z = __shfl_xor_sync(0xffffffffu, k1.z, 16);
                    pk.w = __shfl_xor_sync(0xffffffffu, k1.w, 16);
                    q1v.x = q1v.x * csx + sgn * pq.x * snx;
                    q1v.y = q1v.y * csy + sgn * pq.y * sny;
                    q1v.z = q1v.z * csz + sgn * pq.z * snz;
                    q1v.w = q1v.w * csw + sgn * pq.w * snw;
                    k1.x = k1.x * csx + sgn * pk.x * snx;
                    k1.y = k1.y * csy + sgn * pk.y * sny;
                    k1.z = k1.z * csz + sgn * pk.z * snz;
                    k1.w = k1.w * csw + sgn * pk.w * snw;
                    float d10 = wred(q1v.x * k0.x + q1v.y * k0.y +
                                     q1v.z * k0.z + q1v.w * k0.w);
                    float d11 = wred(q1v.x * k1.x + q1v.y * k1.y +
                                     q1v.z * k1.z + q1v.w * k1.w);
                    const float scale = 0.08838834764831845f;
                    float s10 = d10 * scale, s11 = d11 * scale;
                    float m = fmaxf(s10, s11);
                    float e0 = expf(s10 - m), e1 = expf(s11 - m);
                    float inv = 1.f / (e0 + e1);
                    if ((s & 31) == 0) {   // unique owner writes kv for head
                        float4 v0 = ldcg4(g_qkv + 4096 + hh * HD + 4 * lane);
                        float4 v1 = ldcg4(g_qkv + 4096 + DIM + hh * HD + 4 * lane);
                        float* kv = kvc + (size_t)l * 4096;
                        ((float4*)(kv + hh * 256))[lane] = k0;
                        ((float4*)(kv + hh * 256 + HD))[lane] = k1;
                        ((float4*)(kv + 2048 + hh * 256))[lane] = v0;
                        ((float4*)(kv + 2048 + hh * 256 + HD))[lane] = v1;
                    }
                    __syncwarp();
                    if (lane < 4) {
                        int row = s * 4 + lane;
                        float v0 = ldcg(&g_qkv[4096 + row]);
                        float v1 = ldcg(&g_qkv[4096 + DIM + row]);
                        xs2[si * 4 + lane] =
                            make_float2(v0, (e0 * v0 + e1 * v1) * inv);
                    }
                    __syncwarp();
                }
            }
            CBAR();
            float a00 = 0.f, a01 = 0.f, a10 = 0.f, a11 = 0.f;
            for (int si = 0; si < nst; si++) {
                STAGE_WAIT()
                const float2* bw = (const float2*)buf;
#pragma unroll
                for (int r = 0; r < 4; r++) {
                    float2 w = bw[r * CTHR + tid];
                    float2 x = xs2[si * 4 + r];
                    a00 = fmaf(w.x, x.x, a00); a01 = fmaf(w.y, x.x, a01);
                    a10 = fmaf(w.x, x.y, a10); a11 = fmaf(w.y, x.y, a11);
                }
                STAGE_DONE()
            }
            red2(g_h + 2 * tid, a00, a01);
            red2(g_h + DIM + 2 * tid, a10, a11);
        }
        gbar(2 + 4 * l);

        // ===== GATEUP: all blocks, 13-14 stages of 1 row x 4096 =====
        {
            srange(b, S_GU, s0, s1);
            int nst = s1 - s0;
            float q0 = 0.f, q1 = 0.f;
#pragma unroll
            for (int i = 0; i < 2; i++) {
                int idx = tid + i * CTHR;
                float a = ldcg(&g_h[idx]), c = ldcg(&g_h[DIM + idx]);
                q0 += a * a; q1 += c * c;
            }
            q0 = bred512(q0, sbuf);
            q1 = bred512(q1, sbuf);
            float r0 = rsqrtf(q0 * (1.f / DIM) + EPSF);
            float r1 = rsqrtf(q1 * (1.f / DIM) + EPSF);
            if (b < 12) g_qkv[b * CTHR + tid] = 0.f;   // zero next layer's qkv
            if (tid < nst) {
                int s = s0 + tid;
                int row = s & 1023;
                float wl = ln2[l * DIM + row];
                xs2[tid] = make_float2(ldcg(&g_h[row]) * r0 * wl,
                                       ldcg(&g_h[DIM + row]) * r1 * wl);
            }
            CBAR();
            float4 A00 = {0,0,0,0}, A01 = {0,0,0,0}, A10 = {0,0,0,0}, A11 = {0,0,0,0};
            int curmat = -1;
            for (int si = 0; si < nst; si++) {
                int s = s0 + si;
                int mat = s >> 10;
                if (mat != curmat) {
                    if (curmat >= 0) {
                        float* o = g_gu + curmat * 8192;
                        red4(o + 4 * tid, A00);
                        red4(o + 2048 + 4 * tid, A01);
                        red4(o + FF + 4 * tid, A10);
                        red4(o + FF + 2048 + 4 * tid, A11);
                        A00 = A01 = A10 = A11 = make_float4(0.f, 0.f, 0.f, 0.f);
                    }
                    curmat = mat;
                }
                STAGE_WAIT()
                const float4* b4 = (const float4*)buf;
                float2 x = xs2[si];
                float4 w0 = b4[tid];
                float4 w1 = b4[CTHR + tid];
                A00.x = fmaf(w0.x, x.x, A00.x); A00.y = fmaf(w0.y, x.x, A00.y);
                A00.z = fmaf(w0.z, x.x, A00.z); A00.w = fmaf(w0.w, x.x, A00.w);
                A10.x = fmaf(w0.x, x.y, A10.x); A10.y = fmaf(w0.y, x.y, A10.y);
                A10.z = fmaf(w0.z, x.y, A10.z); A10.w = fmaf(w0.w, x.y, A10.w);
                A01.x = fmaf(w1.x, x.x, A01.x); A01.y = fmaf(w1.y, x.x, A01.y);
                A01.z = fmaf(w1.z, x.x, A01.z); A01.w = fmaf(w1.w, x.x, A01.w);
                A11.x = fmaf(w1.x, x.y, A11.x); A11.y = fmaf(w1.y, x.y, A11.y);
                A11.z = fmaf(w1.z, x.y, A11.z); A11.w = fmaf(w1.w, x.y, A11.w);
                STAGE_DONE()
            }
            if (curmat >= 0) {
                float* o = g_gu + curmat * 8192;
                red4(o + 4 * tid, A00);
                red4(o + 2048 + 4 * tid, A01);
                red4(o + FF + 4 * tid, A10);
                red4(o + FF + 2048 + 4 * tid, A11);
            }
        }
        gbar(3 + 4 * l);

        // ===== DOWN: all blocks, 6-7 stages of 4 rows =====
        {
            srange(b, S_DN, s0, s1);
            int nst = s1 - s0;
            if (tid < 4 * nst) {
                int row = (s0 + (tid >> 2)) * 4 + (tid & 3);
                float g0 = ldcg(&g_gu[row]);
                float g1 = ldcg(&g_gu[FF + row]);
                float u0 = ldcg(&g_gu[8192 + row]);
                float u1 = ldcg(&g_gu[8192 + FF + row]);
                xs2[tid] = make_float2(g0 / (1.f + expf(-g0)) * u0,
                                       g1 / (1.f + expf(-g1)) * u1);
            }
            CBAR();
            float a00 = 0.f, a01 = 0.f, a10 = 0.f, a11 = 0.f;
            for (int si = 0; si < nst; si++) {
                STAGE_WAIT()
                const float2* bw = (const float2*)buf;
#pragma unroll
                for (int r = 0; r < 4; r++) {
                    float2 w = bw[r * CTHR + tid];
                    float2 x = xs2[si * 4 + r];
                    a00 = fmaf(w.x, x.x, a00); a01 = fmaf(w.y, x.x, a01);
                    a10 = fmaf(w.x, x.y, a10); a11 = fmaf(w.y, x.y, a11);
                }
                STAGE_DONE()
            }
            red2(g_h + 2 * tid, a00, a01);
            red2(g_h + DIM + 2 * tid, a10, a11);
        }
        gbar(4 + 4 * l);
    }

    // ===== LM: all blocks, 51-52 stages of 2 rows x 2048 =====
    {
        float s = 0.f;
#pragma unroll
        for (int i = 0; i < 2; i++) {
            float v = ldcg(&g_h[DIM + tid + i * CTHR]);
            s += v * v;
        }
        s = bred512(s, sbuf);
        float r = rsqrtf(s * (1.f / DIM) + EPSF);
#pragma unroll
        for (int i = 0; i < 2; i++) {
            int idx = tid + i * CTHR;
            xsf[idx] = ldcg(&g_h[DIM + idx]) * r * fn[idx];
        }
        CBAR();

        srange(b, S_LM, s0, s1);
        float4 A = {0, 0, 0, 0};
        int curmat = -1;
        for (int si = 0; si < s1 - s0; si++) {
            int s2 = s0 + si;
            int mat = s2 / 512;
            if (mat != curmat) {
                if (curmat >= 0)
                    red4(logits + (size_t)curmat * VOC + 4 * tid, A);
                A = make_float4(0.f, 0.f, 0.f, 0.f);
                curmat = mat;
            }
            int row0 = (s2 % 512) * 2;
            STAGE_WAIT()
            const float4* b4 = (const float4*)buf;
#pragma unroll
            for (int r2 = 0; r2 < 2; r2++) {
                float x = xsf[row0 + r2];
                float4 w = b4[r2 * CTHR + tid];
                A.x = fmaf(w.x, x, A.x); A.y = fmaf(w.y, x, A.y);
                A.z = fmaf(w.z, x, A.z); A.w = fmaf(w.w, x, A.w);
            }
            STAGE_DONE()
        }
        if (curmat >= 0) red4(logits + (size_t)curmat * VOC + 4 * tid, A);
    }

    CBAR();
    if (tid == 0) {
        unsigned old = atomicAdd(&g_fin, 1u);
        if (old == (unsigned)(NBLK - 1)) {
            for (int i = 0; i < 21; i++) g_bar[i] = 0u;
            __threadfence();
            g_fin = 0u;
        }
    }
}

// ---------------- host launcher ----------------
extern "C" void kernel_launch(void* const* d_in, const int* in_sizes, int n_in,
                              void* d_out, int out_size) {
    const float *past, *emb, *Wq, *Wk, *Wv, *Wo, *qn, *kn, *ln1, *ln2, *Wg, *Wu,
        *Wd, *fn, *lm;
    const int* tok;
    if (in_sizes[1] == 1) {
        past = (const float*)d_in[0];
        tok  = (const int*)d_in[1];
        emb  = (const float*)d_in[2];
        Wq = (const float*)d_in[3];  Wk = (const float*)d_in[4];
        Wv = (const float*)d_in[5];  Wo = (const float*)d_in[6];
        qn = (const float*)d_in[7];  kn = (const float*)d_in[8];
        ln1 = (const float*)d_in[9]; ln2 = (const float*)d_in[10];
        Wg = (const float*)d_in[11]; Wu = (const float*)d_in[12];
        Wd = (const float*)d_in[13]; fn = (const float*)d_in[14];
        lm = (const float*)d_in[15];
    } else {
        past = (const float*)d_in[0];
        emb  = (const float*)d_in[1];
        Wq = (const float*)d_in[2];  Wk = (const float*)d_in[3];
        Wv = (const float*)d_in[4];  Wo = (const float*)d_in[5];
        qn = (const float*)d_in[6];  kn = (const float*)d_in[7];
        ln1 = (const float*)d_in[8]; ln2 = (const float*)d_in[9];
        Wg = (const float*)d_in[10]; Wu = (const float*)d_in[11];
        Wd = (const float*)d_in[12]; fn = (const float*)d_in[13];
        lm = (const float*)d_in[14];
        tok = (const int*)d_in[15];
    }

    static bool attr_done = false;
    if (!attr_done) {
        cudaFuncSetAttribute(k_mega, cudaFuncAttributeMaxDynamicSharedMemorySize,
                             SM_TOTAL);
        attr_done = true;
    }

    float* out = (float*)d_out;
    float* logits = out;
    float* kvc = out + NLM * VOC;

    k_mega<<<NBLK, NTHR, SM_TOTAL>>>(past, emb, tok, Wq, Wk, Wv, Wo, qn, kn,
                                     ln1, ln2, Wg, Wu, Wd, fn, lm, logits, kvc);
    (void)n_in; (void)out_size;
}

// round 14
// speedup vs baseline: 1.0876x; 1.0876x over previous
#include <cuda_runtime.h>
#include <cuda_bf16.h>
#include <math.h>
#include <stdint.h>

#define DIM    1024
#define HD     128
#define FF     4096
#define VOC    2048
#define NLM    15
#define NLAYER 5
#define EPSF   1e-6f
#define NBLK   148
#define CTHR   512          // compute threads
#define NTHR   544          // + producer warp
#define NWARP  16

#define NBUF         12
#define STAGE_BYTES  16384
#define STAGE_FLOATS 4096
#define MBF_OFF  0
#define MBE_OFF  96
#define SC_OFF   192
#define XS_OFF   256
#define SBUF_OFF 4352
#define TAB_OFF  4480
#define ST_OFF   8192
#define SM_TOTAL (ST_OFF + NBUF * STAGE_BYTES)   // 204800

#define N_STICKY_MATS 6    // 50MB sticky set (R12 winner)
#define S_LM 7680          // LM stages: 15 mats x 512 stages (2 rows x 2048)

// ---------------- device scratch ----------------
__device__ float g_h[2 * DIM];
__device__ float g_qkv[6 * DIM];
__device__ float g_gu[4 * FF];
__device__ unsigned g_bar[32];
__device__ unsigned g_fin;

// ---------------- PTX helpers ----------------
__device__ __forceinline__ uint32_t s2u(const void* p) {
    uint32_t a;
    asm("{ .reg .u64 t; cvta.to.shared.u64 t, %1; cvt.u32.u64 %0, t; }"
        : "=r"(a) : "l"(p));
    return a;
}
#define MB_INIT(mbar, cnt) \
    asm volatile("mbarrier.init.shared.b64 [%0], %1;" :: "r"(mbar), "r"(cnt) : "memory")
#define MB_EXPECT(mbar, bytes) \
    asm volatile("mbarrier.arrive.expect_tx.shared.b64 _, [%0], %1;" :: "r"(mbar), "r"(bytes) : "memory")
#define MB_ARRIVE(mbar) \
    asm volatile("mbarrier.arrive.shared.b64 _, [%0];" :: "r"(mbar) : "memory")
#define MB_WAIT(mbar, ph) do {                                                   \
    asm volatile("{\n\t.reg .pred P1;\n\t"                                       \
        "W_%=:\n\t"                                                              \
        "mbarrier.try_wait.parity.acquire.cta.shared::cta.b64 P1, [%0], %1, 0x989680;\n\t" \
        "@P1 bra.uni D_%=;\n\t"                                                  \
        "bra.uni W_%=;\n\t"                                                      \
        "D_%=:\n\t}"                                                             \
        :: "r"(mbar), "r"(ph) : "memory");                                       \
} while (0)
#define CBAR() asm volatile("bar.sync 1, %0;" :: "n"(CTHR) : "memory")
__device__ __forceinline__ void bulk_g2s_h(uint32_t dst, const void* src,
                                           uint32_t bytes, uint32_t mbar,
                                           uint64_t pol) {
    asm volatile(
        "cp.async.bulk.shared::cluster.global.mbarrier::complete_tx::bytes"
        ".L2::cache_hint [%0], [%1], %2, [%3], %4;"
        :: "r"(dst), "l"(src), "r"(bytes), "r"(mbar), "l"(pol) : "memory");
}
__device__ __forceinline__ void red2(float* p, float a, float b) {
    asm volatile("red.global.add.v2.f32 [%0], {%1, %2};"
                 :: "l"(p), "f"(a), "f"(b) : "memory");
}
__device__ __forceinline__ void red4(float* p, float4 v) {
    asm volatile("red.global.add.v4.f32 [%0], {%1, %2, %3, %4};"
                 :: "l"(p), "f"(v.x), "f"(v.y), "f"(v.z), "f"(v.w) : "memory");
}
__device__ __forceinline__ float ldcg(const float* p) {
    float v;
    asm volatile("ld.global.cg.f32 %0, [%1];" : "=f"(v) : "l"(p));
    return v;
}
__device__ __forceinline__ float4 ldcg4(const float* p) {
    float4 v;
    asm volatile("ld.global.cg.v4.f32 {%0,%1,%2,%3}, [%4];"
                 : "=f"(v.x), "=f"(v.y), "=f"(v.z), "=f"(v.w) : "l"(p));
    return v;
}

// ---------------- reductions ----------------
__device__ __forceinline__ float wred(float v) {
#pragma unroll
    for (int o = 16; o > 0; o >>= 1) v += __shfl_xor_sync(0xffffffffu, v, o);
    return v;
}
__device__ __forceinline__ float bred512(float v, float* sbuf) {
    int tid = threadIdx.x;
#pragma unroll
    for (int o = 16; o > 0; o >>= 1) v += __shfl_down_sync(0xffffffffu, v, o);
    if ((tid & 31) == 0) sbuf[tid >> 5] = v;
    CBAR();
    if (tid < 32) {
        float r = (tid < 16) ? sbuf[tid] : 0.f;
#pragma unroll
        for (int o = 8; o > 0; o >>= 1) r += __shfl_down_sync(0xffffffffu, r, o);
        if (tid == 0) sbuf[0] = r;
    }
    CBAR();
    float r = sbuf[0];
    CBAR();
    return r;
}

__device__ __forceinline__ void gbar(int idx) {
    __threadfence();
    CBAR();
    if (threadIdx.x == 0) {
        atomicAdd(&g_bar[idx], 1u);
        unsigned v;
        while (true) {
            asm volatile("ld.acquire.gpu.global.u32 %0, [%1];"
                         : "=r"(v) : "l"(&g_bar[idx]) : "memory");
            if (v >= (unsigned)NBLK) break;
            __nanosleep(64);
        }
    }
    CBAR();
}

// consume: per-warp arrivals, warps pipeline freely
#define CONSUME_BEGIN(nst)                                                     \
    for (int _i = 0; _i < (nst); _i++) {                                       \
        int _slot = consumed % NBUF, _par = (consumed / NBUF) & 1;             \
        MB_WAIT(mbf + 8u * _slot, _par);                                       \
        const float* buf = (const float*)(sm + ST_OFF + _slot * STAGE_BYTES);

#define CONSUME_END                                                            \
        __syncwarp();                                                          \
        if ((tid & 31) == 0) MB_ARRIVE(mbe + 8u * _slot);                      \
        consumed++;                                                            \
    }

#define STAGE_WAIT()                                                           \
    int _slot = consumed % NBUF, _par = (consumed / NBUF) & 1;                 \
    MB_WAIT(mbf + 8u * _slot, _par);                                           \
    const float* buf = (const float*)(sm + ST_OFF + _slot * STAGE_BYTES);
#define STAGE_DONE()                                                           \
    __syncwarp();                                                              \
    if ((tid & 31) == 0) MB_ARRIVE(mbe + 8u * _slot);                          \
    consumed++;

// ---------------- mega kernel ----------------
__global__ void __launch_bounds__(NTHR) k_mega(
    const float* __restrict__ past, const float* __restrict__ emb,
    const int* __restrict__ tok,
    const float* __restrict__ Wq, const float* __restrict__ Wk,
    const float* __restrict__ Wv, const float* __restrict__ Wo,
    const float* __restrict__ qn, const float* __restrict__ kn,
    const float* __restrict__ ln1, const float* __restrict__ ln2,
    const float* __restrict__ Wg, const float* __restrict__ Wu,
    const float* __restrict__ Wd, const float* __restrict__ fn,
    const float* __restrict__ lm,
    float* __restrict__ logits, float* __restrict__ kvc) {
    extern __shared__ char sm[];
    const int b = blockIdx.x;
    const int tid = threadIdx.x;
    const uint32_t mbf = s2u(sm) + MBF_OFF;
    const uint32_t mbe = s2u(sm) + MBE_OFF;
    float* sbuf = (float*)(sm + SBUF_OFF);
    float2* xs2 = (float2*)(sm + XS_OFF);
    float* xsf = (float*)(sm + XS_OFF);
    float* sc = (float*)(sm + SC_OFF);
    int lms0 = (b * S_LM) / NBLK, lms1 = ((b + 1) * S_LM) / NBLK;  // LM stages

    if (tid == CTHR) {
#pragma unroll
        for (int s = 0; s < NBUF; s++) {
            MB_INIT(mbf + 8u * s, 1);
            MB_INIT(mbe + 8u * s, NWARP);
        }
    }
    __syncthreads();

    // ================= producer warp =================
    if (tid >= CTHR) {
        if (tid == CTHR) {
            uint64_t pol_keep, pol_stream;
            asm volatile("createpolicy.fractional.L2::evict_last.b64 %0, 1.0;"
                         : "=l"(pol_keep));
            asm volatile("createpolicy.fractional.L2::evict_first.b64 %0, 1.0;"
                         : "=l"(pol_stream));
            uintptr_t* tab = (uintptr_t*)(sm + TAB_OFF);
            int n = 0;
            for (int l = 0; l < NLAYER; l++) {
                if (b < 96) {
                    const float* W = (b >> 5) == 0 ? Wq : ((b >> 5) == 1 ? Wk : Wv);
                    const float* base = W + (size_t)l * DIM * DIM +
                                        (size_t)(b & 31) * 32 * DIM;
                    for (int s = 0; s < 8; s++)
                        tab[n++] = (uintptr_t)(base + (size_t)s * STAGE_FLOATS);
                }
                if (b < 64) {
                    const float* base = Wo + (size_t)l * DIM * DIM +
                                        (size_t)b * 16 * DIM;
                    for (int s = 0; s < 4; s++)
                        tab[n++] = (uintptr_t)(base + (size_t)s * STAGE_FLOATS);
                }
                if (b < 128) {
                    const float* W = (b >> 6) ? Wu : Wg;
                    const float* base = W + (size_t)l * DIM * FF +
                                        (size_t)(b & 63) * 16 * FF;
                    for (int s = 0; s < 16; s++)
                        tab[n++] = (uintptr_t)(base + (size_t)s * STAGE_FLOATS);
                }
                if (b < 128) {
                    const float* base = Wd + (size_t)l * FF * DIM +
                                        (size_t)b * 32 * DIM;
                    for (int s = 0; s < 8; s++)
                        tab[n++] = (uintptr_t)(base + (size_t)s * STAGE_FLOATS);
                }
            }
            for (int s = lms0; s < lms1; s++) {   // LM: stage-granular
                int mat = s >> 9;                  // 512 stages per mat
                uintptr_t flag = (mat < N_STICKY_MATS) ? 1u : 0u;
                tab[n++] = ((uintptr_t)(lm + (size_t)mat * DIM * VOC +
                                        (size_t)(s & 511) * 2 * VOC)) | flag;
            }
            for (int i = 0; i < n; i++) {
                int slot = i % NBUF;
                if (i >= NBUF) {
                    int par = ((i / NBUF) - 1) & 1;
                    MB_WAIT(mbe + 8u * slot, par);
                }
                uintptr_t e = tab[i];
                uint64_t pol = (e & 1u) ? pol_keep : pol_stream;
                const void* src = (const void*)(e & ~(uintptr_t)1u);
                MB_EXPECT(mbf + 8u * slot, STAGE_BYTES);
                bulk_g2s_h(s2u(sm) + ST_OFF + slot * STAGE_BYTES, src,
                           STAGE_BYTES, mbf + 8u * slot, pol);
            }
        }
        return;
    }

    // ================= compute threads (512) =================
    int consumed = 0;

    {
        int gi = b * CTHR + tid;
        if (gi < NLM * VOC) logits[gi] = 0.f;
        else if (gi < NLM * VOC + 6 * DIM) g_qkv[gi - NLM * VOC] = 0.f;
        else if (gi < NLM * VOC + 6 * DIM + DIM) {
            int i = gi - (NLM * VOC + 6 * DIM);
            g_h[i] = past[i];
        } else if (gi < NLM * VOC + 6 * DIM + 2 * DIM) {
            int i = gi - (NLM * VOC + 7 * DIM);
            g_h[DIM + i] = emb[(size_t)tok[0] * DIM + i];
        }
    }
    gbar(0);

    for (int l = 0; l < NLAYER; l++) {
        // ===== QKV =====
        if (b < 96) {
            int mat = b >> 5, rch = b & 31;
            float s0 = 0.f, s1 = 0.f;
#pragma unroll
            for (int i = 0; i < 2; i++) {
                int idx = tid + i * CTHR;
                float a = ldcg(&g_h[idx]), c = ldcg(&g_h[DIM + idx]);
                s0 += a * a; s1 += c * c;
            }
            s0 = bred512(s0, sbuf);
            s1 = bred512(s1, sbuf);
            float r0 = rsqrtf(s0 * (1.f / DIM) + EPSF);
            float r1 = rsqrtf(s1 * (1.f / DIM) + EPSF);
            if (tid < 32) {
                int idx = rch * 32 + tid;
                float wl = ln1[l * DIM + idx];
                xs2[tid] = make_float2(ldcg(&g_h[idx]) * r0 * wl,
                                       ldcg(&g_h[DIM + idx]) * r1 * wl);
            }
            CBAR();
            float a00 = 0.f, a01 = 0.f, a10 = 0.f, a11 = 0.f;
            CONSUME_BEGIN(8)
                const float2* bw = (const float2*)buf;
#pragma unroll
                for (int r = 0; r < 4; r++) {
                    float2 w = bw[r * CTHR + tid];
                    float2 x = xs2[_i * 4 + r];
                    a00 = fmaf(w.x, x.x, a00); a01 = fmaf(w.y, x.x, a01);
                    a10 = fmaf(w.x, x.y, a10); a11 = fmaf(w.y, x.y, a11);
                }
            CONSUME_END
            float* o = g_qkv + mat * 2048;
            red2(o + 2 * tid, a00, a01);
            red2(o + DIM + 2 * tid, a10, a11);
        } else if (b < 128) {
            g_gu[(b - 96) * CTHR + tid] = 0.f;
        }
        gbar(1 + 4 * l);

        // ===== WO + attention =====
        if (b < 64) {
            int hh = b >> 3;
            if (tid < 32) {
                int lane = tid;
                float4 q1 = ldcg4(g_qkv + DIM + hh * HD + 4 * lane);
                float4 k0 = ldcg4(g_qkv + 2048 + hh * HD + 4 * lane);
                float4 k1 = ldcg4(g_qkv + 2048 + DIM + hh * HD + 4 * lane);
                float nq1 = wred(q1.x * q1.x + q1.y * q1.y + q1.z * q1.z + q1.w * q1.w);
                float nk0 = wred(k0.x * k0.x + k0.y * k0.y + k0.z * k0.z + k0.w * k0.w);
                float nk1 = wred(k1.x * k1.x + k1.y * k1.y + k1.z * k1.z + k1.w * k1.w);
                float rq1 = rsqrtf(nq1 * (1.f / HD) + EPSF);
                float rk0 = rsqrtf(nk0 * (1.f / HD) + EPSF);
                float rk1 = rsqrtf(nk1 * (1.f / HD) + EPSF);
                float4 qn4 = ((const float4*)(qn + l * HD))[lane];
                float4 kn4 = ((const float4*)(kn + l * HD))[lane];
                q1.x *= rq1 * qn4.x; q1.y *= rq1 * qn4.y;
                q1.z *= rq1 * qn4.z; q1.w *= rq1 * qn4.w;
                k0.x *= rk0 * kn4.x; k0.y *= rk0 * kn4.y;
                k0.z *= rk0 * kn4.z; k0.w *= rk0 * kn4.w;
                k1.x *= rk1 * kn4.x; k1.y *= rk1 * kn4.y;
                k1.z *= rk1 * kn4.z; k1.w *= rk1 * kn4.w;
                int jb = 4 * (lane & 15);
                const float C = 9.210340371976184f / 64.f;
                float an0 = expf(-(float)(jb + 0) * C);
                float an1 = expf(-(float)(jb + 1) * C);
                float an2 = expf(-(float)(jb + 2) * C);
                float an3 = expf(-(float)(jb + 3) * C);
                float csx = cosf(an0), snx = sinf(an0);
                float csy = cosf(an1), sny = sinf(an1);
                float csz = cosf(an2), snz = sinf(an2);
                float csw = cosf(an3), snw = sinf(an3);
                float sgn = (lane < 16) ? -1.f : 1.f;
                float4 pq, pk;
                pq.x = __shfl_xor_sync(0xffffffffu, q1.x, 16);
                pq.y = __shfl_xor_sync(0xffffffffu, q1.y, 16);
                pq.z = __shfl_xor_sync(0xffffffffu, q1.z, 16);
                pq.w = __shfl_xor_sync(0xffffffffu, q1.w, 16);
                pk.x = __shfl_xor_sync(0xffffffffu, k1.x, 16);
                pk.y = __shfl_xor_sync(0xffffffffu, k1.y, 16);
                pk.z = __shfl_xor_sync(0xffffffffu, k1.z, 16);
                pk.w = __shfl_xor_sync(0xffffffffu, k1.w, 16);
                q1.x = q1.x * csx + sgn * pq.x * snx;
                q1.y = q1.y * csy + sgn * pq.y * sny;
                q1.z = q1.z * csz + sgn * pq.z * snz;
                q1.w = q1.w * csw + sgn * pq.w * snw;
                k1.x = k1.x * csx + sgn * pk.x * snx;
                k1.y = k1.y * csy + sgn * pk.y * sny;
                k1.z = k1.z * csz + sgn * pk.z * snz;
                k1.w = k1.w * csw + sgn * pk.w * snw;
                float d10 = wred(q1.x * k0.x + q1.y * k0.y + q1.z * k0.z + q1.w * k0.w);
                float d11 = wred(q1.x * k1.x + q1.y * k1.y + q1.z * k1.z + q1.w * k1.w);
                const float scale = 0.08838834764831845f;
                float s10 = d10 * scale, s11 = d11 * scale;
                float m = fmaxf(s10, s11);
                float e0 = expf(s10 - m), e1 = expf(s11 - m);
                float inv = 1.f / (e0 + e1);
                if (lane == 0) { sc[0] = e0; sc[1] = e1; sc[2] = inv; }
                if ((b & 7) == 0) {
                    float4 v0 = ldcg4(g_qkv + 4096 + hh * HD + 4 * lane);
                    float4 v1 = ldcg4(g_qkv + 4096 + DIM + hh * HD + 4 * lane);
                    float* kv = kvc + (size_t)l * 4096;
                    ((float4*)(kv + hh * 256))[lane] = k0;
                    ((float4*)(kv + hh * 256 + HD))[lane] = k1;
                    ((float4*)(kv + 2048 + hh * 256))[lane] = v0;
                    ((float4*)(kv + 2048 + hh * 256 + HD))[lane] = v1;
                }
            }
            CBAR();
            if (tid < 16) {
                int dim = b * 16 + tid;
                float v0 = ldcg(&g_qkv[4096 + dim]);
                float v1 = ldcg(&g_qkv[4096 + DIM + dim]);
                xs2[tid] = make_float2(v0, (sc[0] * v0 + sc[1] * v1) * sc[2]);
            }
            CBAR();
            float a00 = 0.f, a01 = 0.f, a10 = 0.f, a11 = 0.f;
            CONSUME_BEGIN(4)
                const float2* bw = (const float2*)buf;
#pragma unroll
                for (int r = 0; r < 4; r++) {
                    float2 w = bw[r * CTHR + tid];
                    float2 x = xs2[_i * 4 + r];
                    a00 = fmaf(w.x, x.x, a00); a01 = fmaf(w.y, x.x, a01);
                    a10 = fmaf(w.x, x.y, a10); a11 = fmaf(w.y, x.y, a11);
                }
            CONSUME_END
            red2(g_h + 2 * tid, a00, a01);
            red2(g_h + DIM + 2 * tid, a10, a11);
        }
        gbar(2 + 4 * l);

        // ===== GATEUP =====
        if (b < 128) {
            int mat = b >> 6, rch = b & 63;
            float s0 = 0.f, s1 = 0.f;
#pragma unroll
            for (int i = 0; i < 2; i++) {
                int idx = tid + i * CTHR;
                float a = ldcg(&g_h[idx]), c = ldcg(&g_h[DIM + idx]);
                s0 += a * a; s1 += c * c;
            }
            s0 = bred512(s0, sbuf);
            s1 = bred512(s1, sbuf);
            float r0 = rsqrtf(s0 * (1.f / DIM) + EPSF);
            float r1 = rsqrtf(s1 * (1.f / DIM) + EPSF);
            if (tid < 16) {
                int idx = rch * 16 + tid;
                float wl = ln2[l * DIM + idx];
                xs2[tid] = make_float2(ldcg(&g_h[idx]) * r0 * wl,
                                       ldcg(&g_h[DIM + idx]) * r1 * wl);
            }
            CBAR();
            float4 A00 = {0,0,0,0}, A01 = {0,0,0,0}, A10 = {0,0,0,0}, A11 = {0,0,0,0};
            CONSUME_BEGIN(16)
                const float4* b4 = (const float4*)buf;
                float2 x = xs2[_i];
                float4 w0 = b4[tid];
                float4 w1 = b4[CTHR + tid];
                A00.x = fmaf(w0.x, x.x, A00.x); A00.y = fmaf(w0.y, x.x, A00.y);
                A00.z = fmaf(w0.z, x.x, A00.z); A00.w = fmaf(w0.w, x.x, A00.w);
                A10.x = fmaf(w0.x, x.y, A10.x); A10.y = fmaf(w0.y, x.y, A10.y);
                A10.z = fmaf(w0.z, x.y, A10.z); A10.w = fmaf(w0.w, x.y, A10.w);
                A01.x = fmaf(w1.x, x.x, A01.x); A01.y = fmaf(w1.y, x.x, A01.y);
                A01.z = fmaf(w1.z, x.x, A01.z); A01.w = fmaf(w1.w, x.x, A01.w);
                A11.x = fmaf(w1.x, x.y, A11.x); A11.y = fmaf(w1.y, x.y, A11.y);
                A11.z = fmaf(w1.z, x.y, A11.z); A11.w = fmaf(w1.w, x.y, A11.w);
            CONSUME_END
            float* o = g_gu + mat * 8192;
            red4(o + 4 * tid, A00);
            red4(o + 2048 + 4 * tid, A01);
            red4(o + FF + 4 * tid, A10);
            red4(o + FF + 2048 + 4 * tid, A11);
        }
        gbar(3 + 4 * l);

        // ===== DOWN =====
        if (b < 128) {
            if (tid < 32) {
                int idx = b * 32 + tid;
                float g0 = ldcg(&g_gu[idx]);
                float g1 = ldcg(&g_gu[FF + idx]);
                float u0 = ldcg(&g_gu[8192 + idx]);
                float u1 = ldcg(&g_gu[8192 + FF + idx]);
                xs2[tid] = make_float2(g0 / (1.f + expf(-g0)) * u0,
                                       g1 / (1.f + expf(-g1)) * u1);
            }
            CBAR();
            float a00 = 0.f, a01 = 0.f, a10 = 0.f, a11 = 0.f;
            CONSUME_BEGIN(8)
                const float2* bw = (const float2*)buf;
#pragma unroll
                for (int r = 0; r < 4; r++) {
                    float2 w = bw[r * CTHR + tid];
                    float2 x = xs2[_i * 4 + r];
                    a00 = fmaf(w.x, x.x, a00); a01 = fmaf(w.y, x.x, a01);
                    a10 = fmaf(w.x, x.y, a10); a11 = fmaf(w.y, x.y, a11);
                }
            CONSUME_END
            red2(g_h + 2 * tid, a00, a01);
            red2(g_h + DIM + 2 * tid, a10, a11);
        }
        if (b < 12) g_qkv[b * CTHR + tid] = 0.f;
        gbar(4 + 4 * l);
    }

    // ===== LM: stage-granular split (51-52 stages of 2 rows x 2048) =====
    {
        float s = 0.f;
#pragma unroll
        for (int i = 0; i < 2; i++) {
            float v = ldcg(&g_h[DIM + tid + i * CTHR]);
            s += v * v;
        }
        s = bred512(s, sbuf);
        float r = rsqrtf(s * (1.f / DIM) + EPSF);
#pragma unroll
        for (int i = 0; i < 2; i++) {
            int idx = tid + i * CTHR;
            xsf[idx] = ldcg(&g_h[DIM + idx]) * r * fn[idx];
        }
        CBAR();

        float4 A = {0, 0, 0, 0};
        int curmat = -1;
        for (int s2 = lms0; s2 < lms1; s2++) {
            int mat = s2 >> 9;
            if (mat != curmat) {
                if (curmat >= 0)
                    red4(logits + (size_t)curmat * VOC + 4 * tid, A);
                A = make_float4(0.f, 0.f, 0.f, 0.f);
                curmat = mat;
            }
            int row0 = (s2 & 511) * 2;
            STAGE_WAIT()
            const float4* b4 = (const float4*)buf;
#pragma unroll
            for (int r2 = 0; r2 < 2; r2++) {
                float x = xsf[row0 + r2];
                float4 w = b4[r2 * CTHR + tid];
                A.x = fmaf(w.x, x, A.x); A.y = fmaf(w.y, x, A.y);
                A.z = fmaf(w.z, x, A.z); A.w = fmaf(w.w, x, A.w);
            }
            STAGE_DONE()
        }
        if (curmat >= 0) red4(logits + (size_t)curmat * VOC + 4 * tid, A);
    }

    CBAR();
    if (tid == 0) {
        unsigned old = atomicAdd(&g_fin, 1u);
        if (old == (unsigned)(NBLK - 1)) {
            for (int i = 0; i < 21; i++) g_bar[i] = 0u;
            __threadfence();
            g_fin = 0u;
        }
    }
}

// ---------------- host launcher ----------------
extern "C" void kernel_launch(void* const* d_in, const int* in_sizes, int n_in,
                              void* d_out, int out_size) {
    const float *past, *emb, *Wq, *Wk, *Wv, *Wo, *qn, *kn, *ln1, *ln2, *Wg, *Wu,
        *Wd, *fn, *lm;
    const int* tok;
    if (in_sizes[1] == 1) {
        past = (const float*)d_in[0];
        tok  = (const int*)d_in[1];
        emb  = (const float*)d_in[2];
        Wq = (const float*)d_in[3];  Wk = (const float*)d_in[4];
        Wv = (const float*)d_in[5];  Wo = (const float*)d_in[6];
        qn = (const float*)d_in[7];  kn = (const float*)d_in[8];
        ln1 = (const float*)d_in[9]; ln2 = (const float*)d_in[10];
        Wg = (const float*)d_in[11]; Wu = (const float*)d_in[12];
        Wd = (const float*)d_in[13]; fn = (const float*)d_in[14];
        lm = (const float*)d_in[15];
    } else {
        past = (const float*)d_in[0];
        emb  = (const float*)d_in[1];
        Wq = (const float*)d_in[2];  Wk = (const float*)d_in[3];
        Wv = (const float*)d_in[4];  Wo = (const float*)d_in[5];
        qn = (const float*)d_in[6];  kn = (const float*)d_in[7];
        ln1 = (const float*)d_in[8]; ln2 = (const float*)d_in[9];
        Wg = (const float*)d_in[10]; Wu = (const float*)d_in[11];
        Wd = (const float*)d_in[12]; fn = (const float*)d_in[13];
        lm = (const float*)d_in[14];
        tok = (const int*)d_in[15];
    }

    static bool attr_done = false;
    if (!attr_done) {
        cudaFuncSetAttribute(k_mega, cudaFuncAttributeMaxDynamicSharedMemorySize,
                             SM_TOTAL);
        attr_done = true;
    }

    float* out = (float*)d_out;
    float* logits = out;
    float* kvc = out + NLM * VOC;

    k_mega<<<NBLK, NTHR, SM_TOTAL>>>(past, emb, tok, Wq, Wk, Wv, Wo, qn, kn,
                                     ln1, ln2, Wg, Wu, Wd, fn, lm, logits, kvc);
    (void)n_in; (void)out_size;
}